// round 2
// baseline (speedup 1.0000x reference)
#include <cuda_runtime.h>
#include <cstdint>
#include <cstdio>

#define N_NODES 100000
#define D 128
#define NB 64          // nodes per group in fused kernel
#define SROW 132       // padded smem row stride (floats)

// Scratch: aggregate buffer (module-load allocation, allowed)
__device__ float g_agg[(size_t)N_NODES * D];
__device__ int g_idx64;        // 1 if edge indices are int64, 0 if int32
__device__ int g_mask_stride;  // bytes per mask element (1, 4, or 8)

// ---------------------------------------------------------------------------
// Detect edge-index width AND mask element stride.
// Edge indices: all valid < 100000 << 2^32, so int32 data read as int64 is
// >= 2^32 with overwhelming probability over 512 probes.
// Mask: OR-reduce which byte residues (mod 8) carry nonzero values over the
// first 8KB. bool/uint8 ones -> all residues nonzero -> stride 1.
// int32 ones -> residues {0,4} -> stride 4. int64 ones -> residue {0} -> 8.
// All-zero mask -> stride 1 (safe: reads in-bounds, values are 0 anyway).
// ---------------------------------------------------------------------------
__global__ void detect_kernel(const unsigned long long* src,
                              const unsigned char* mask) {
    __shared__ int bad;
    __shared__ int nzres;
    if (threadIdx.x == 0) { bad = 0; nzres = 0; }
    __syncthreads();
    for (int i = threadIdx.x; i < 1024; i += blockDim.x) {
        if (src[i] >= (unsigned long long)N_NODES) bad = 1;
    }
    for (int i = threadIdx.x; i < 8192; i += blockDim.x) {
        if (mask[i]) atomicOr(&nzres, 1 << (i & 7));
    }
    __syncthreads();
    if (threadIdx.x == 0) {
        g_idx64 = bad ? 0 : 1;
        int m = nzres;
        int stride;
        if (m == 0)            stride = 1;  // all zeros: stride irrelevant
        else if (m & 0xAA)     stride = 1;  // any odd residue -> byte mask
        else if (m & 0x44)     stride = 2;  // residue 2 or 6 -> int16 (unlikely)
        else if (m & 0x10)     stride = 4;  // residue 4 -> int32
        else                   stride = 8;  // only residue 0 -> int64
        g_mask_stride = stride;
    }
}

// ---------------------------------------------------------------------------
// Zero the aggregate buffer.
// ---------------------------------------------------------------------------
__global__ void zero_kernel() {
    size_t n = (size_t)N_NODES * D / 4;
    float4* p = (float4*)g_agg;
    float4 z = make_float4(0.f, 0.f, 0.f, 0.f);
    for (size_t i = (size_t)blockIdx.x * blockDim.x + threadIdx.x; i < n;
         i += (size_t)gridDim.x * blockDim.x)
        p[i] = z;
}

// ---------------------------------------------------------------------------
// Scatter-add: one warp per edge. Each lane handles 4 floats (float4),
// reduced into g_agg via red.global.add.v4.f32 (16B vector atomic, no return).
// ---------------------------------------------------------------------------
__global__ void scatter_kernel(const void* __restrict__ src_idx,
                               const void* __restrict__ dst_idx,
                               const float* __restrict__ feat,
                               int n_edges) {
    int warp = (int)((blockIdx.x * (size_t)blockDim.x + threadIdx.x) >> 5);
    int lane = threadIdx.x & 31;
    if (warp >= n_edges) return;

    long long s, d;
    if (g_idx64) {
        s = ((const long long*)src_idx)[warp];
        d = ((const long long*)dst_idx)[warp];
    } else {
        s = ((const int*)src_idx)[warp];
        d = ((const int*)dst_idx)[warp];
    }

    float4 v = ((const float4*)feat)[s * (D / 4) + lane];
    float* p = g_agg + (size_t)d * D + lane * 4;
    asm volatile("red.global.add.v4.f32 [%0], {%1,%2,%3,%4};"
                 :: "l"(p), "f"(v.x), "f"(v.y), "f"(v.z), "f"(v.w)
                 : "memory");
}

// ---------------------------------------------------------------------------
// Fused: h = feat + mask*agg ; inv_norm ; out = (h @ W^T) * inv_norm + b
// Persistent blocks. W staged once per block in padded smem.
// Tile: 256 threads, NB=64 nodes/group. Thread (tcol = t&15, trow = t>>4)
// computes outputs o = tcol + 16*k (k<8) for nodes trow*4 + j (j<4).
// Strided o mapping keeps float4 W smem reads conflict-free per quarter-warp.
// ---------------------------------------------------------------------------
__global__ __launch_bounds__(256)
void fused_kernel(const float* __restrict__ feat,
                  const unsigned char* __restrict__ mask,
                  const float* __restrict__ W,
                  const float* __restrict__ b,
                  float* __restrict__ out,
                  int num_groups) {
    extern __shared__ float sm[];
    float* Wsm   = sm;                     // 128 * SROW floats
    float* Hs    = sm + 128 * SROW;        // NB * SROW floats
    float* inorm = Hs + NB * SROW;         // NB floats

    int t = threadIdx.x;
    int tcol = t & 15;
    int trow = t >> 4;
    int mstride = g_mask_stride;

    // Stage W (row-major [128][128]) into padded smem, once per block.
    for (int idx = t; idx < 128 * 128; idx += 256) {
        int r = idx >> 7, c = idx & 127;
        Wsm[r * SROW + c] = W[idx];
    }
    // Bias for my 8 output columns.
    float bb[8];
#pragma unroll
    for (int k = 0; k < 8; k++) bb[k] = b[tcol + 16 * k];
    __syncthreads();

    for (int g = blockIdx.x; g < num_groups; g += gridDim.x) {
        int base = g * NB;

        // Load h tile into smem.
        for (int idx = t; idx < NB * D; idx += 256) {
            int nl = idx >> 7, c = idx & 127;
            int n = base + nl;
            float h = 0.f;
            if (n < N_NODES) {
                h = feat[(size_t)n * D + c];
                if (mask[(size_t)n * mstride]) h += g_agg[(size_t)n * D + c];
            }
            Hs[nl * SROW + c] = h;
        }
        __syncthreads();

        // Per-node inverse norms (threads 0..63).
        if (t < NB) {
            const float4* hp = (const float4*)(Hs + t * SROW);
            float s = 0.f;
#pragma unroll
            for (int i = 0; i < D / 4; i++) {
                float4 v = hp[i];
                s += v.x * v.x + v.y * v.y + v.z * v.z + v.w * v.w;
            }
            inorm[t] = 1.f / fmaxf(sqrtf(s), 1e-12f);
        }
        __syncthreads();

        // Register-tiled dot products: 8 outputs x 4 nodes per thread.
        float acc[4][8];
#pragma unroll
        for (int j = 0; j < 4; j++)
#pragma unroll
            for (int k = 0; k < 8; k++) acc[j][k] = 0.f;

        const float* hbase = Hs + (trow * 4) * SROW;
        for (int i = 0; i < D; i += 4) {
            float4 w4[8];
#pragma unroll
            for (int k = 0; k < 8; k++)
                w4[k] = *(const float4*)(Wsm + (tcol + 16 * k) * SROW + i);
#pragma unroll
            for (int j = 0; j < 4; j++) {
                float4 h4 = *(const float4*)(hbase + j * SROW + i);
#pragma unroll
                for (int k = 0; k < 8; k++) {
                    acc[j][k] += h4.x * w4[k].x + h4.y * w4[k].y +
                                 h4.z * w4[k].z + h4.w * w4[k].w;
                }
            }
        }

        // Epilogue: scale by inv_norm, add bias, store.
#pragma unroll
        for (int j = 0; j < 4; j++) {
            int nl = trow * 4 + j;
            int n = base + nl;
            if (n < N_NODES) {
                float inv = inorm[nl];
#pragma unroll
                for (int k = 0; k < 8; k++)
                    out[(size_t)n * D + tcol + 16 * k] = acc[j][k] * inv + bb[k];
            }
        }
        __syncthreads();
    }
}

// ---------------------------------------------------------------------------
extern "C" void kernel_launch(void* const* d_in, const int* in_sizes, int n_in,
                              void* d_out, int out_size) {
    const float*         feat = (const float*)d_in[0];
    const void*          esrc = d_in[1];
    const void*          edst = d_in[2];
    const unsigned char* mask = (const unsigned char*)d_in[3];
    const float*         W    = (const float*)d_in[4];
    const float*         b    = (const float*)d_in[5];
    float*               out  = (float*)d_out;
    int n_edges = in_sizes[1];

    detect_kernel<<<1, 256>>>((const unsigned long long*)esrc, mask);
    zero_kernel<<<4096, 256>>>();

    int scatter_blocks = (n_edges + 7) / 8;   // 8 warps (edges) per 256-thread block
    scatter_kernel<<<scatter_blocks, 256>>>(esrc, edst, feat, n_edges);

    int num_groups = (N_NODES + NB - 1) / NB;
    size_t smem = (size_t)(128 * SROW + NB * SROW + NB) * sizeof(float);
    cudaFuncSetAttribute(fused_kernel,
                         cudaFuncAttributeMaxDynamicSharedMemorySize,
                         (int)smem);
    fused_kernel<<<304, 256, smem>>>(feat, mask, W, b, out, num_groups);
}

// round 4
// speedup vs baseline: 1.7713x; 1.7713x over previous
#include <cuda_runtime.h>
#include <cstdint>

#define N_NODES 100000
#define D 128
#define MAX_E 1600000
#define NPAD 102400            // 400 * 256, padded node count for scan
#define SCAN_BLKS 400
#define NB 64                  // nodes per GEMM tile
#define SROW 132               // padded smem row stride (floats)
#define NUM_TILES ((N_NODES + NB - 1) / NB)

// ---- scratch (module-load allocations, allowed) ----
__device__ float g_h[(size_t)N_NODES * D];   // normalized h rows
__device__ int g_cnt[NPAD];
__device__ int g_off[NPAD];                  // exclusive CSR offsets
__device__ int g_cur[NPAD];                  // placement cursors
__device__ int g_bsum[SCAN_BLKS];
__device__ int g_sorted[MAX_E];              // src indices grouped by dst
__device__ int g_idx64;                      // edge index width flag
__device__ int g_mask_stride;                // bytes per mask element

// ---------------------------------------------------------------------------
// Detect edge-index width (int32 vs int64) and mask element stride.
// ---------------------------------------------------------------------------
__global__ void detect_kernel(const unsigned long long* src,
                              const unsigned char* mask) {
    __shared__ int bad, nzres;
    if (threadIdx.x == 0) { bad = 0; nzres = 0; }
    __syncthreads();
    for (int i = threadIdx.x; i < 1024; i += blockDim.x)
        if (src[i] >= (unsigned long long)N_NODES) bad = 1;
    for (int i = threadIdx.x; i < 8192; i += blockDim.x)
        if (mask[i]) atomicOr(&nzres, 1 << (i & 7));
    __syncthreads();
    if (threadIdx.x == 0) {
        g_idx64 = bad ? 0 : 1;
        int m = nzres, s;
        if (m == 0)        s = 1;
        else if (m & 0xAA) s = 1;
        else if (m & 0x44) s = 2;
        else if (m & 0x10) s = 4;
        else               s = 8;
        g_mask_stride = s;
    }
}

__global__ void zero_cnt_kernel() {
    int i = blockIdx.x * blockDim.x + threadIdx.x;
    if (i < NPAD) g_cnt[i] = 0;
}

// ---------------------------------------------------------------------------
// Histogram of destination degrees.
// ---------------------------------------------------------------------------
__global__ void hist_kernel(const void* __restrict__ dst_idx, int n_edges) {
    int e = blockIdx.x * blockDim.x + threadIdx.x;
    if (e >= n_edges) return;
    int d = g_idx64 ? (int)((const long long*)dst_idx)[e]
                    : ((const int*)dst_idx)[e];
    atomicAdd(&g_cnt[d], 1);
}

// ---------------------------------------------------------------------------
// 3-phase exclusive scan over g_cnt -> g_off (and cursor copy).
// ---------------------------------------------------------------------------
__global__ void scan1_kernel() {
    __shared__ int s[256];
    int t = threadIdx.x, gid = blockIdx.x * 256 + t;
    int v = g_cnt[gid];
    s[t] = v;
    __syncthreads();
#pragma unroll
    for (int o = 1; o < 256; o <<= 1) {
        int x = (t >= o) ? s[t - o] : 0;
        __syncthreads();
        s[t] += x;
        __syncthreads();
    }
    g_off[gid] = s[t] - v;
    if (t == 255) g_bsum[blockIdx.x] = s[255];
}

__global__ void scan2_kernel() {
    __shared__ int s[512];
    int t = threadIdx.x;
    int v = (t < SCAN_BLKS) ? g_bsum[t] : 0;
    s[t] = v;
    __syncthreads();
#pragma unroll
    for (int o = 1; o < 512; o <<= 1) {
        int x = (t >= o) ? s[t - o] : 0;
        __syncthreads();
        s[t] += x;
        __syncthreads();
    }
    if (t < SCAN_BLKS) g_bsum[t] = s[t] - v;
}

__global__ void scan3_kernel() {
    int t = threadIdx.x, gid = blockIdx.x * 256 + t;
    int o = g_off[gid] + g_bsum[blockIdx.x];
    g_off[gid] = o;
    g_cur[gid] = o;
}

// ---------------------------------------------------------------------------
// Placement: bucket src indices by dst (counting sort, order-free).
// ---------------------------------------------------------------------------
__global__ void place_kernel(const void* __restrict__ src_idx,
                             const void* __restrict__ dst_idx, int n_edges) {
    int e = blockIdx.x * blockDim.x + threadIdx.x;
    if (e >= n_edges) return;
    int s, d;
    if (g_idx64) {
        s = (int)((const long long*)src_idx)[e];
        d = (int)((const long long*)dst_idx)[e];
    } else {
        s = ((const int*)src_idx)[e];
        d = ((const int*)dst_idx)[e];
    }
    int pos = atomicAdd(&g_cur[d], 1);
    g_sorted[pos] = s;
}

// ---------------------------------------------------------------------------
// Gather + mask + add self + L2-normalize, one warp per node.
// Lane holds 4 columns (float4). Writes normalized h row to g_h.
// ---------------------------------------------------------------------------
__global__ __launch_bounds__(256)
void gather_norm_kernel(const float* __restrict__ feat,
                        const unsigned char* __restrict__ mask) {
    int warp = blockIdx.x * 8 + (threadIdx.x >> 5);
    int lane = threadIdx.x & 31;
    if (warp >= N_NODES) return;
    int n = warp;
    int mstride = g_mask_stride;

    float4 acc = ((const float4*)feat)[(size_t)n * 32 + lane];

    if (mask[(size_t)n * mstride]) {
        int beg = g_off[n], end = g_off[n + 1];
        int e = beg;
        for (; e + 4 <= end; e += 4) {
            int s0 = g_sorted[e + 0], s1 = g_sorted[e + 1];
            int s2 = g_sorted[e + 2], s3 = g_sorted[e + 3];
            float4 v0 = ((const float4*)feat)[(size_t)s0 * 32 + lane];
            float4 v1 = ((const float4*)feat)[(size_t)s1 * 32 + lane];
            float4 v2 = ((const float4*)feat)[(size_t)s2 * 32 + lane];
            float4 v3 = ((const float4*)feat)[(size_t)s3 * 32 + lane];
            acc.x += v0.x + v1.x + v2.x + v3.x;
            acc.y += v0.y + v1.y + v2.y + v3.y;
            acc.z += v0.z + v1.z + v2.z + v3.z;
            acc.w += v0.w + v1.w + v2.w + v3.w;
        }
        for (; e < end; e++) {
            int s0 = g_sorted[e];
            float4 v0 = ((const float4*)feat)[(size_t)s0 * 32 + lane];
            acc.x += v0.x; acc.y += v0.y; acc.z += v0.z; acc.w += v0.w;
        }
    }

    float ss = acc.x * acc.x + acc.y * acc.y + acc.z * acc.z + acc.w * acc.w;
#pragma unroll
    for (int o = 16; o > 0; o >>= 1) ss += __shfl_xor_sync(0xFFFFFFFFu, ss, o);
    float inv = 1.f / fmaxf(sqrtf(ss), 1e-12f);

    float4 r;
    r.x = acc.x * inv; r.y = acc.y * inv; r.z = acc.z * inv; r.w = acc.w * inv;
    ((float4*)g_h)[(size_t)n * 32 + lane] = r;
}

// ---------------------------------------------------------------------------
// GEMM: out = g_h @ W^T + b.  128 threads/block, NB=64 nodes per tile.
// Thread (tcol = t&15, trow = t>>4): outputs o = tcol+16k (k<8),
// nodes trow*8+j (j<8). 64 accumulators, 16 LDS.128 per 256 FMA.
// W staged once per block (persistent blocks).
// ---------------------------------------------------------------------------
__global__ __launch_bounds__(128)
void gemm_kernel(const float* __restrict__ W,
                 const float* __restrict__ b,
                 float* __restrict__ out) {
    extern __shared__ float sm[];
    float* Wsm = sm;                  // 128 * SROW
    float* Hs  = sm + 128 * SROW;     // NB * SROW

    int t = threadIdx.x;
    int tcol = t & 15;
    int trow = t >> 4;

    // Stage W (row-major [128][128]) into padded smem.
    for (int idx = t; idx < 128 * 32; idx += 128) {
        int r = idx >> 5, c4 = idx & 31;
        *(float4*)&Wsm[r * SROW + c4 * 4] = ((const float4*)W)[idx];
    }
    float bb[8];
#pragma unroll
    for (int k = 0; k < 8; k++) bb[k] = b[tcol + 16 * k];
    __syncthreads();

    for (int g = blockIdx.x; g < NUM_TILES; g += gridDim.x) {
        int base = g * NB;

        // Load normalized h tile.
        for (int idx = t; idx < NB * 32; idx += 128) {
            int nl = idx >> 5, c4 = idx & 31;
            int n = base + nl;
            float4 v = make_float4(0.f, 0.f, 0.f, 0.f);
            if (n < N_NODES) v = ((const float4*)g_h)[(size_t)n * 32 + c4];
            *(float4*)&Hs[nl * SROW + c4 * 4] = v;
        }
        __syncthreads();

        float acc[8][8];
#pragma unroll
        for (int j = 0; j < 8; j++)
#pragma unroll
            for (int k = 0; k < 8; k++) acc[j][k] = 0.f;

        const float* hbase = Hs + (trow * 8) * SROW;
        for (int i = 0; i < D; i += 4) {
            float4 w4[8];
#pragma unroll
            for (int k = 0; k < 8; k++)
                w4[k] = *(const float4*)(Wsm + (tcol + 16 * k) * SROW + i);
#pragma unroll
            for (int j = 0; j < 8; j++) {
                float4 h4 = *(const float4*)(hbase + j * SROW + i);
#pragma unroll
                for (int k = 0; k < 8; k++) {
                    acc[j][k] += h4.x * w4[k].x + h4.y * w4[k].y +
                                 h4.z * w4[k].z + h4.w * w4[k].w;
                }
            }
        }

#pragma unroll
        for (int j = 0; j < 8; j++) {
            int n = base + trow * 8 + j;
            if (n < N_NODES) {
#pragma unroll
                for (int k = 0; k < 8; k++)
                    out[(size_t)n * D + tcol + 16 * k] = acc[j][k] + bb[k];
            }
        }
        __syncthreads();
    }
}

// ---------------------------------------------------------------------------
extern "C" void kernel_launch(void* const* d_in, const int* in_sizes, int n_in,
                              void* d_out, int out_size) {
    const float*         feat = (const float*)d_in[0];
    const void*          esrc = d_in[1];
    const void*          edst = d_in[2];
    const unsigned char* mask = (const unsigned char*)d_in[3];
    const float*         W    = (const float*)d_in[4];
    const float*         b    = (const float*)d_in[5];
    float*               out  = (float*)d_out;
    int n_edges = in_sizes[1];

    detect_kernel<<<1, 256>>>((const unsigned long long*)esrc, mask);
    zero_cnt_kernel<<<NPAD / 256, 256>>>();

    int eblk = (n_edges + 255) / 256;
    hist_kernel<<<eblk, 256>>>(edst, n_edges);
    scan1_kernel<<<SCAN_BLKS, 256>>>();
    scan2_kernel<<<1, 512>>>();
    scan3_kernel<<<SCAN_BLKS, 256>>>();
    place_kernel<<<eblk, 256>>>(esrc, edst, n_edges);

    gather_norm_kernel<<<(N_NODES + 7) / 8, 256>>>(feat, mask);

    size_t smem = (size_t)(128 * SROW + NB * SROW) * sizeof(float);
    cudaFuncSetAttribute(gemm_kernel,
                         cudaFuncAttributeMaxDynamicSharedMemorySize,
                         (int)smem);
    gemm_kernel<<<296, 128, smem>>>(W, b, out);
}

// round 5
// speedup vs baseline: 1.9146x; 1.0809x over previous
#include <cuda_runtime.h>
#include <cstdint>

#define N_NODES 100000
#define D 128
#define MAX_E 1600000
#define NPAD 102400            // 400 * 256, padded node count for scan
#define SCAN_BLKS 400
#define NB 64                  // nodes per GEMM tile
#define SROW 132               // padded smem row stride (floats)
#define NUM_TILES ((N_NODES + NB - 1) / NB)

typedef unsigned long long ull;

// ---- scratch (module-load allocations, allowed) ----
__device__ float g_h[(size_t)N_NODES * D];   // normalized h rows
__device__ int g_cnt[NPAD];
__device__ int g_off[NPAD];                  // exclusive CSR offsets
__device__ int g_cur[NPAD];                  // placement cursors
__device__ int g_bsum[SCAN_BLKS];
__device__ int g_sorted[MAX_E];              // src indices grouped by dst
__device__ int g_idx64;                      // edge index width flag
__device__ int g_mask_stride;                // bytes per mask element

// Packed fp32x2 FMA (sm_100+ base PTX feature; doubles fp32 rate).
__device__ __forceinline__ ull ffma2(ull a, ull b, ull c) {
    ull d;
    asm("fma.rn.f32x2 %0, %1, %2, %3;" : "=l"(d) : "l"(a), "l"(b), "l"(c));
    return d;
}
__device__ __forceinline__ float fold2(ull v) {
    float lo, hi;
    asm("mov.b64 {%0,%1}, %2;" : "=f"(lo), "=f"(hi) : "l"(v));
    return lo + hi;
}

// ---------------------------------------------------------------------------
// Detect edge-index width (int32 vs int64) and mask element stride.
// ---------------------------------------------------------------------------
__global__ void detect_kernel(const unsigned long long* src,
                              const unsigned char* mask) {
    __shared__ int bad, nzres;
    if (threadIdx.x == 0) { bad = 0; nzres = 0; }
    __syncthreads();
    for (int i = threadIdx.x; i < 1024; i += blockDim.x)
        if (src[i] >= (unsigned long long)N_NODES) bad = 1;
    for (int i = threadIdx.x; i < 8192; i += blockDim.x)
        if (mask[i]) atomicOr(&nzres, 1 << (i & 7));
    __syncthreads();
    if (threadIdx.x == 0) {
        g_idx64 = bad ? 0 : 1;
        int m = nzres, s;
        if (m == 0)        s = 1;
        else if (m & 0xAA) s = 1;
        else if (m & 0x44) s = 2;
        else if (m & 0x10) s = 4;
        else               s = 8;
        g_mask_stride = s;
    }
}

__global__ void zero_cnt_kernel() {
    int i = blockIdx.x * blockDim.x + threadIdx.x;
    if (i < NPAD) g_cnt[i] = 0;
}

__global__ void hist_kernel(const void* __restrict__ dst_idx, int n_edges) {
    int e = blockIdx.x * blockDim.x + threadIdx.x;
    if (e >= n_edges) return;
    int d = g_idx64 ? (int)((const long long*)dst_idx)[e]
                    : ((const int*)dst_idx)[e];
    atomicAdd(&g_cnt[d], 1);
}

// ---------------------------------------------------------------------------
// 3-phase exclusive scan over g_cnt -> g_off (and cursor copy).
// ---------------------------------------------------------------------------
__global__ void scan1_kernel() {
    __shared__ int s[256];
    int t = threadIdx.x, gid = blockIdx.x * 256 + t;
    int v = g_cnt[gid];
    s[t] = v;
    __syncthreads();
#pragma unroll
    for (int o = 1; o < 256; o <<= 1) {
        int x = (t >= o) ? s[t - o] : 0;
        __syncthreads();
        s[t] += x;
        __syncthreads();
    }
    g_off[gid] = s[t] - v;
    if (t == 255) g_bsum[blockIdx.x] = s[255];
}

__global__ void scan2_kernel() {
    __shared__ int s[512];
    int t = threadIdx.x;
    int v = (t < SCAN_BLKS) ? g_bsum[t] : 0;
    s[t] = v;
    __syncthreads();
#pragma unroll
    for (int o = 1; o < 512; o <<= 1) {
        int x = (t >= o) ? s[t - o] : 0;
        __syncthreads();
        s[t] += x;
        __syncthreads();
    }
    if (t < SCAN_BLKS) g_bsum[t] = s[t] - v;
}

__global__ void scan3_kernel() {
    int t = threadIdx.x, gid = blockIdx.x * 256 + t;
    int o = g_off[gid] + g_bsum[blockIdx.x];
    g_off[gid] = o;
    g_cur[gid] = o;
}

// ---------------------------------------------------------------------------
// Placement: bucket src indices by dst (counting sort, order-free).
// ---------------------------------------------------------------------------
__global__ void place_kernel(const void* __restrict__ src_idx,
                             const void* __restrict__ dst_idx, int n_edges) {
    int e = blockIdx.x * blockDim.x + threadIdx.x;
    if (e >= n_edges) return;
    int s, d;
    if (g_idx64) {
        s = (int)((const long long*)src_idx)[e];
        d = (int)((const long long*)dst_idx)[e];
    } else {
        s = ((const int*)src_idx)[e];
        d = ((const int*)dst_idx)[e];
    }
    int pos = atomicAdd(&g_cur[d], 1);
    g_sorted[pos] = s;
}

// ---------------------------------------------------------------------------
// Gather + mask + add self + L2-normalize, one warp per node.
// ---------------------------------------------------------------------------
__global__ __launch_bounds__(256)
void gather_norm_kernel(const float* __restrict__ feat,
                        const unsigned char* __restrict__ mask) {
    int warp = blockIdx.x * 8 + (threadIdx.x >> 5);
    int lane = threadIdx.x & 31;
    if (warp >= N_NODES) return;
    int n = warp;
    int mstride = g_mask_stride;

    float4 acc = ((const float4*)feat)[(size_t)n * 32 + lane];

    if (mask[(size_t)n * mstride]) {
        int beg = g_off[n], end = g_off[n + 1];
        int e = beg;
        for (; e + 4 <= end; e += 4) {
            int s0 = g_sorted[e + 0], s1 = g_sorted[e + 1];
            int s2 = g_sorted[e + 2], s3 = g_sorted[e + 3];
            float4 v0 = ((const float4*)feat)[(size_t)s0 * 32 + lane];
            float4 v1 = ((const float4*)feat)[(size_t)s1 * 32 + lane];
            float4 v2 = ((const float4*)feat)[(size_t)s2 * 32 + lane];
            float4 v3 = ((const float4*)feat)[(size_t)s3 * 32 + lane];
            acc.x += v0.x + v1.x + v2.x + v3.x;
            acc.y += v0.y + v1.y + v2.y + v3.y;
            acc.z += v0.z + v1.z + v2.z + v3.z;
            acc.w += v0.w + v1.w + v2.w + v3.w;
        }
        for (; e < end; e++) {
            int s0 = g_sorted[e];
            float4 v0 = ((const float4*)feat)[(size_t)s0 * 32 + lane];
            acc.x += v0.x; acc.y += v0.y; acc.z += v0.z; acc.w += v0.w;
        }
    }

    float ss = acc.x * acc.x + acc.y * acc.y + acc.z * acc.z + acc.w * acc.w;
#pragma unroll
    for (int o = 16; o > 0; o >>= 1) ss += __shfl_xor_sync(0xFFFFFFFFu, ss, o);
    float inv = 1.f / fmaxf(sqrtf(ss), 1e-12f);

    float4 r;
    r.x = acc.x * inv; r.y = acc.y * inv; r.z = acc.z * inv; r.w = acc.w * inv;
    ((float4*)g_h)[(size_t)n * 32 + lane] = r;
}

// ---------------------------------------------------------------------------
// GEMM: out = g_h @ W^T + b.  128 threads/block, NB=64 nodes per tile.
// Thread (tcol = t&15, trow = t>>4): outputs o = tcol+16k (k<8),
// nodes trow*8+j (j<8). 64 f32x2 accumulators: each holds
// (sum over even-K, sum over odd-K) partials, folded at the end.
// Both FFMA2 operands are contiguous 8B chunks of the row-major smem tiles
// (loaded as ulonglong2 = one LDS.128) -> zero packing overhead.
// ---------------------------------------------------------------------------
__global__ __launch_bounds__(128)
void gemm_kernel(const float* __restrict__ W,
                 const float* __restrict__ b,
                 float* __restrict__ out) {
    extern __shared__ float sm[];
    float* Wsm = sm;                  // 128 * SROW
    float* Hs  = sm + 128 * SROW;     // NB * SROW

    int t = threadIdx.x;
    int tcol = t & 15;
    int trow = t >> 4;

    // Stage W (row-major [128][128]) into padded smem.
    for (int idx = t; idx < 128 * 32; idx += 128) {
        int r = idx >> 5, c4 = idx & 31;
        *(float4*)&Wsm[r * SROW + c4 * 4] = ((const float4*)W)[idx];
    }
    float bb[8];
#pragma unroll
    for (int k = 0; k < 8; k++) bb[k] = b[tcol + 16 * k];
    __syncthreads();

    for (int g = blockIdx.x; g < NUM_TILES; g += gridDim.x) {
        int base = g * NB;

        // Load normalized h tile.
        for (int idx = t; idx < NB * 32; idx += 128) {
            int nl = idx >> 5, c4 = idx & 31;
            int n = base + nl;
            float4 v = make_float4(0.f, 0.f, 0.f, 0.f);
            if (n < N_NODES) v = ((const float4*)g_h)[(size_t)n * 32 + c4];
            *(float4*)&Hs[nl * SROW + c4 * 4] = v;
        }
        __syncthreads();

        ull acc[8][8];
#pragma unroll
        for (int j = 0; j < 8; j++)
#pragma unroll
            for (int k = 0; k < 8; k++) acc[j][k] = 0ull;

        const float* hbase = Hs + (trow * 8) * SROW;
        for (int i = 0; i < D; i += 4) {
            ulonglong2 w2[8];
#pragma unroll
            for (int k = 0; k < 8; k++)
                w2[k] = *(const ulonglong2*)(Wsm + (tcol + 16 * k) * SROW + i);
#pragma unroll
            for (int j = 0; j < 8; j++) {
                ulonglong2 h2 = *(const ulonglong2*)(hbase + j * SROW + i);
#pragma unroll
                for (int k = 0; k < 8; k++) {
                    acc[j][k] = ffma2(h2.x, w2[k].x, acc[j][k]);
                    acc[j][k] = ffma2(h2.y, w2[k].y, acc[j][k]);
                }
            }
        }

#pragma unroll
        for (int j = 0; j < 8; j++) {
            int n = base + trow * 8 + j;
            if (n < N_NODES) {
#pragma unroll
                for (int k = 0; k < 8; k++)
                    out[(size_t)n * D + tcol + 16 * k] = fold2(acc[j][k]) + bb[k];
            }
        }
        __syncthreads();
    }
}

// ---------------------------------------------------------------------------
extern "C" void kernel_launch(void* const* d_in, const int* in_sizes, int n_in,
                              void* d_out, int out_size) {
    const float*         feat = (const float*)d_in[0];
    const void*          esrc = d_in[1];
    const void*          edst = d_in[2];
    const unsigned char* mask = (const unsigned char*)d_in[3];
    const float*         W    = (const float*)d_in[4];
    const float*         b    = (const float*)d_in[5];
    float*               out  = (float*)d_out;
    int n_edges = in_sizes[1];

    detect_kernel<<<1, 256>>>((const unsigned long long*)esrc, mask);
    zero_cnt_kernel<<<NPAD / 256, 256>>>();

    int eblk = (n_edges + 255) / 256;
    hist_kernel<<<eblk, 256>>>(edst, n_edges);
    scan1_kernel<<<SCAN_BLKS, 256>>>();
    scan2_kernel<<<1, 512>>>();
    scan3_kernel<<<SCAN_BLKS, 256>>>();
    place_kernel<<<eblk, 256>>>(esrc, edst, n_edges);

    gather_norm_kernel<<<(N_NODES + 7) / 8, 256>>>(feat, mask);

    size_t smem = (size_t)(128 * SROW + NB * SROW) * sizeof(float);
    cudaFuncSetAttribute(gemm_kernel,
                         cudaFuncAttributeMaxDynamicSharedMemorySize,
                         (int)smem);
    gemm_kernel<<<296, 128, smem>>>(W, b, out);
}

// round 6
// speedup vs baseline: 2.3558x; 1.2304x over previous
#include <cuda_runtime.h>
#include <cstdint>

#define N_NODES 100000
#define D 128
#define MAX_E 1600000
#define NPAD 102400            // 400 * 256, padded node count for scan
#define SCAN_BLKS 400
#define NB 64                  // nodes per GEMM tile
#define WS 132                 // padded smem row stride (floats); bank=(4r+c)%32
#define NUM_TILES ((N_NODES + NB - 1) / NB)

// ---- scratch (module-load allocations, allowed) ----
__device__ float g_h[(size_t)N_NODES * D];   // normalized h rows (tf32-rounded)
__device__ int g_cnt[NPAD];
__device__ int g_off[NPAD];                  // block-local exclusive offsets
__device__ int g_cur[NPAD];                  // placement cursors (block-local)
__device__ int g_bsum[SCAN_BLKS];            // exclusive block sums
__device__ int g_sorted[MAX_E];              // src indices grouped by dst
__device__ int g_idx64;                      // edge index width flag
__device__ int g_mask_stride;                // bytes per mask element

__device__ __forceinline__ float f2tf32f(float f) {
    uint32_t r;
    asm("cvt.rna.tf32.f32 %0, %1;" : "=r"(r) : "f"(f));
    return __uint_as_float(r);
}

// ---------------------------------------------------------------------------
// Detect edge-index width + mask stride (block 0) AND zero g_cnt (all blocks).
// ---------------------------------------------------------------------------
__global__ void detect_zero_kernel(const unsigned long long* src,
                                   const unsigned char* mask) {
    int gid = blockIdx.x * blockDim.x + threadIdx.x;
    if (gid < NPAD) g_cnt[gid] = 0;
    if (blockIdx.x != 0) return;
    __shared__ int bad, nzres;
    if (threadIdx.x == 0) { bad = 0; nzres = 0; }
    __syncthreads();
    for (int i = threadIdx.x; i < 1024; i += blockDim.x)
        if (src[i] >= (unsigned long long)N_NODES) bad = 1;
    for (int i = threadIdx.x; i < 8192; i += blockDim.x)
        if (mask[i]) atomicOr(&nzres, 1 << (i & 7));
    __syncthreads();
    if (threadIdx.x == 0) {
        g_idx64 = bad ? 0 : 1;
        int m = nzres, s;
        if (m == 0)        s = 1;
        else if (m & 0xAA) s = 1;
        else if (m & 0x44) s = 2;
        else if (m & 0x10) s = 4;
        else               s = 8;
        g_mask_stride = s;
    }
}

__global__ void hist_kernel(const void* __restrict__ dst_idx, int n_edges) {
    int e = blockIdx.x * blockDim.x + threadIdx.x;
    if (e >= n_edges) return;
    int d = g_idx64 ? (int)((const long long*)dst_idx)[e]
                    : ((const int*)dst_idx)[e];
    atomicAdd(&g_cnt[d], 1);
}

// Block-local exclusive scan; writes partial offsets + cursors + block totals.
__global__ void scan1_kernel() {
    __shared__ int s[256];
    int t = threadIdx.x, gid = blockIdx.x * 256 + t;
    int v = g_cnt[gid];
    s[t] = v;
    __syncthreads();
#pragma unroll
    for (int o = 1; o < 256; o <<= 1) {
        int x = (t >= o) ? s[t - o] : 0;
        __syncthreads();
        s[t] += x;
        __syncthreads();
    }
    int excl = s[t] - v;
    g_off[gid] = excl;
    g_cur[gid] = excl;
    if (t == 255) g_bsum[blockIdx.x] = s[255];
}

// Exclusive scan of block sums (in place).
__global__ void scan2_kernel() {
    __shared__ int s[512];
    int t = threadIdx.x;
    int v = (t < SCAN_BLKS) ? g_bsum[t] : 0;
    s[t] = v;
    __syncthreads();
#pragma unroll
    for (int o = 1; o < 512; o <<= 1) {
        int x = (t >= o) ? s[t - o] : 0;
        __syncthreads();
        s[t] += x;
        __syncthreads();
    }
    if (t < SCAN_BLKS) g_bsum[t] = s[t] - v;
}

// Placement: bucket src by dst; absolute index = local cursor + block base.
__global__ void place_kernel(const void* __restrict__ src_idx,
                             const void* __restrict__ dst_idx, int n_edges) {
    int e = blockIdx.x * blockDim.x + threadIdx.x;
    if (e >= n_edges) return;
    int s, d;
    if (g_idx64) {
        s = (int)((const long long*)src_idx)[e];
        d = (int)((const long long*)dst_idx)[e];
    } else {
        s = ((const int*)src_idx)[e];
        d = ((const int*)dst_idx)[e];
    }
    int pos = atomicAdd(&g_cur[d], 1) + g_bsum[d >> 8];
    g_sorted[pos] = s;
}

// ---------------------------------------------------------------------------
// Gather + mask + add self + L2-normalize; store tf32-rounded h rows.
// One warp per node, lane holds 4 columns.
// ---------------------------------------------------------------------------
__global__ __launch_bounds__(256)
void gather_norm_kernel(const float* __restrict__ feat,
                        const unsigned char* __restrict__ mask) {
    int n = blockIdx.x * 8 + (threadIdx.x >> 5);
    int lane = threadIdx.x & 31;
    if (n >= N_NODES) return;
    int mstride = g_mask_stride;

    float4 acc = ((const float4*)feat)[(size_t)n * 32 + lane];

    if (mask[(size_t)n * mstride]) {
        int beg = g_off[n] + g_bsum[n >> 8];
        int end = g_off[n + 1] + g_bsum[(n + 1) >> 8];
        int e = beg;
        for (; e + 4 <= end; e += 4) {
            int s0 = g_sorted[e + 0], s1 = g_sorted[e + 1];
            int s2 = g_sorted[e + 2], s3 = g_sorted[e + 3];
            float4 v0 = ((const float4*)feat)[(size_t)s0 * 32 + lane];
            float4 v1 = ((const float4*)feat)[(size_t)s1 * 32 + lane];
            float4 v2 = ((const float4*)feat)[(size_t)s2 * 32 + lane];
            float4 v3 = ((const float4*)feat)[(size_t)s3 * 32 + lane];
            acc.x += v0.x + v1.x + v2.x + v3.x;
            acc.y += v0.y + v1.y + v2.y + v3.y;
            acc.z += v0.z + v1.z + v2.z + v3.z;
            acc.w += v0.w + v1.w + v2.w + v3.w;
        }
        for (; e < end; e++) {
            int s0 = g_sorted[e];
            float4 v0 = ((const float4*)feat)[(size_t)s0 * 32 + lane];
            acc.x += v0.x; acc.y += v0.y; acc.z += v0.z; acc.w += v0.w;
        }
    }

    float ss = acc.x * acc.x + acc.y * acc.y + acc.z * acc.z + acc.w * acc.w;
#pragma unroll
    for (int o = 16; o > 0; o >>= 1) ss += __shfl_xor_sync(0xFFFFFFFFu, ss, o);
    float inv = 1.f / fmaxf(sqrtf(ss), 1e-12f);

    float4 r;
    r.x = f2tf32f(acc.x * inv);
    r.y = f2tf32f(acc.y * inv);
    r.z = f2tf32f(acc.z * inv);
    r.w = f2tf32f(acc.w * inv);
    ((float4*)g_h)[(size_t)n * 32 + lane] = r;
}

// ---------------------------------------------------------------------------
// GEMM via mma.sync.m16n8k8.tf32 (legacy HMMA path, sm_80+ base PTX).
// Block: 128 threads = 4 warps, tile = 64 nodes x 128 outputs.
// Warp (wm=wid&1, wn=wid>>1): 32 nodes x 64 outputs = 2 m-tiles x 8 n-tiles.
// Fragment LDS with stride WS=132: bank = (4*row + col) mod 32 -> conflict-free.
// ---------------------------------------------------------------------------
__device__ __forceinline__ void mma_tf32(float* d, const uint32_t* a,
                                         uint32_t b0, uint32_t b1) {
    asm volatile(
        "mma.sync.aligned.m16n8k8.row.col.f32.tf32.tf32.f32 "
        "{%0,%1,%2,%3}, {%4,%5,%6,%7}, {%8,%9}, {%0,%1,%2,%3};"
        : "+f"(d[0]), "+f"(d[1]), "+f"(d[2]), "+f"(d[3])
        : "r"(a[0]), "r"(a[1]), "r"(a[2]), "r"(a[3]), "r"(b0), "r"(b1));
}

__global__ __launch_bounds__(128)
void gemm_kernel(const float* __restrict__ W,
                 const float* __restrict__ b,
                 float* __restrict__ out) {
    extern __shared__ float sm[];
    float* Wsm = sm;                  // 128 * WS
    float* Hs  = sm + 128 * WS;       // 64 * WS
    float* bsm = Hs + NB * WS;        // 128

    int t = threadIdx.x;
    int lane = t & 31, wid = t >> 5;
    int grp = lane >> 2, tg = lane & 3;
    int wm = wid & 1, wn = wid >> 1;

    // Stage W (tf32-rounded) once per block.
    for (int idx = t; idx < 128 * 128; idx += 128) {
        int r = idx >> 7, c = idx & 127;
        Wsm[r * WS + c] = f2tf32f(W[idx]);
    }
    if (t < 128) bsm[t] = b[t];
    __syncthreads();

    for (int g = blockIdx.x; g < NUM_TILES; g += gridDim.x) {
        int base = g * NB;

        // Stage normalized h tile (already tf32-rounded).
        for (int idx = t; idx < NB * 32; idx += 128) {
            int nl = idx >> 5, c4 = idx & 31;
            int n = base + nl;
            float4 v = make_float4(0.f, 0.f, 0.f, 0.f);
            if (n < N_NODES) v = ((const float4*)g_h)[(size_t)n * 32 + c4];
            *(float4*)&Hs[nl * WS + c4 * 4] = v;
        }
        __syncthreads();

        float d[2][8][4];
#pragma unroll
        for (int mt = 0; mt < 2; mt++)
#pragma unroll
            for (int nt = 0; nt < 8; nt++)
#pragma unroll
                for (int q = 0; q < 4; q++) d[mt][nt][q] = 0.f;

#pragma unroll
        for (int ks = 0; ks < 16; ks++) {
            int k0 = ks * 8;
            uint32_t a[2][4];
#pragma unroll
            for (int mt = 0; mt < 2; mt++) {
                const float* ar = Hs + (wm * 32 + mt * 16 + grp) * WS + k0 + tg;
                a[mt][0] = __float_as_uint(ar[0]);
                a[mt][1] = __float_as_uint(ar[8 * WS]);
                a[mt][2] = __float_as_uint(ar[4]);
                a[mt][3] = __float_as_uint(ar[8 * WS + 4]);
            }
#pragma unroll
            for (int nt = 0; nt < 8; nt++) {
                const float* br = Wsm + (wn * 64 + nt * 8 + grp) * WS + k0 + tg;
                uint32_t b0 = __float_as_uint(br[0]);
                uint32_t b1 = __float_as_uint(br[4]);
                mma_tf32(d[0][nt], a[0], b0, b1);
                mma_tf32(d[1][nt], a[1], b0, b1);
            }
        }

        // Epilogue: add bias, float2 stores.
#pragma unroll
        for (int mt = 0; mt < 2; mt++) {
            int r0 = base + wm * 32 + mt * 16 + grp;
            int r1 = r0 + 8;
#pragma unroll
            for (int nt = 0; nt < 8; nt++) {
                int col = wn * 64 + nt * 8 + 2 * tg;
                float2 bias = *(float2*)&bsm[col];
                if (r0 < N_NODES) {
                    float2 v = make_float2(d[mt][nt][0] + bias.x,
                                           d[mt][nt][1] + bias.y);
                    *(float2*)&out[(size_t)r0 * D + col] = v;
                }
                if (r1 < N_NODES) {
                    float2 v = make_float2(d[mt][nt][2] + bias.x,
                                           d[mt][nt][3] + bias.y);
                    *(float2*)&out[(size_t)r1 * D + col] = v;
                }
            }
        }
        __syncthreads();
    }
}

// ---------------------------------------------------------------------------
extern "C" void kernel_launch(void* const* d_in, const int* in_sizes, int n_in,
                              void* d_out, int out_size) {
    const float*         feat = (const float*)d_in[0];
    const void*          esrc = d_in[1];
    const void*          edst = d_in[2];
    const unsigned char* mask = (const unsigned char*)d_in[3];
    const float*         W    = (const float*)d_in[4];
    const float*         b    = (const float*)d_in[5];
    float*               out  = (float*)d_out;
    int n_edges = in_sizes[1];

    detect_zero_kernel<<<NPAD / 256, 256>>>((const unsigned long long*)esrc, mask);

    int eblk = (n_edges + 255) / 256;
    hist_kernel<<<eblk, 256>>>(edst, n_edges);
    scan1_kernel<<<SCAN_BLKS, 256>>>();
    scan2_kernel<<<1, 512>>>();
    place_kernel<<<eblk, 256>>>(esrc, edst, n_edges);

    gather_norm_kernel<<<(N_NODES + 7) / 8, 256>>>(feat, mask);

    size_t smem = (size_t)(128 * WS + NB * WS + 128) * sizeof(float);
    cudaFuncSetAttribute(gemm_kernel,
                         cudaFuncAttributeMaxDynamicSharedMemorySize,
                         (int)smem);
    gemm_kernel<<<296, 128, smem>>>(W, b, out);
}

// round 7
// speedup vs baseline: 2.3987x; 1.0182x over previous
#include <cuda_runtime.h>
#include <cuda_fp16.h>
#include <cstdint>

#define N_NODES 100000
#define D 128
#define MAX_E 1600000
#define NPAD 102400            // 400 * 256, padded node count for scan
#define SCAN_BLKS 400
#define NB 64                  // nodes per GEMM tile
#define WS 132                 // padded smem row stride (floats); bank=(4r+c)%32
#define NUM_TILES ((N_NODES + NB - 1) / NB)

// ---- scratch (module-load allocations, allowed) ----
__device__ float g_h[(size_t)N_NODES * D];     // normalized h rows (tf32-rounded)
__device__ __half2 g_fh[(size_t)N_NODES * 64]; // fp16-packed features
__device__ int g_cnt[NPAD];
__device__ int g_off[NPAD];                    // block-local exclusive offsets
__device__ int g_cur[NPAD];                    // placement cursors (block-local)
__device__ int g_bsum[SCAN_BLKS];              // exclusive block sums
__device__ int g_sorted[MAX_E];                // src indices grouped by dst
__device__ int g_idx64;                        // edge index width flag
__device__ int g_mask_stride;                  // bytes per mask element

__device__ __forceinline__ float f2tf32f(float f) {
    uint32_t r;
    asm("cvt.rna.tf32.f32 %0, %1;" : "=r"(r) : "f"(f));
    return __uint_as_float(r);
}

// ---------------------------------------------------------------------------
// Fused prologue: zero g_cnt, detect dtypes (block 0), convert feat -> fp16.
// ---------------------------------------------------------------------------
__global__ void prologue_kernel(const unsigned long long* src,
                                const unsigned char* mask,
                                const float* __restrict__ feat) {
    int gid = blockIdx.x * blockDim.x + threadIdx.x;
    if (gid < NPAD) g_cnt[gid] = 0;

    // fp32 -> half2 conversion, grid-stride over 6.4M half2.
    const float2* f2 = (const float2*)feat;
    int total = N_NODES * 64;
    for (int i = gid; i < total; i += gridDim.x * blockDim.x) {
        float2 v = f2[i];
        g_fh[i] = __floats2half2_rn(v.x, v.y);
    }

    if (blockIdx.x != 0) return;
    __shared__ int bad, nzres;
    if (threadIdx.x == 0) { bad = 0; nzres = 0; }
    __syncthreads();
    for (int i = threadIdx.x; i < 1024; i += blockDim.x)
        if (src[i] >= (unsigned long long)N_NODES) bad = 1;
    for (int i = threadIdx.x; i < 8192; i += blockDim.x)
        if (mask[i]) atomicOr(&nzres, 1 << (i & 7));
    __syncthreads();
    if (threadIdx.x == 0) {
        g_idx64 = bad ? 0 : 1;
        int m = nzres, s;
        if (m == 0)        s = 1;
        else if (m & 0xAA) s = 1;
        else if (m & 0x44) s = 2;
        else if (m & 0x10) s = 4;
        else               s = 8;
        g_mask_stride = s;
    }
}

__global__ void hist_kernel(const void* __restrict__ dst_idx, int n_edges) {
    int e = blockIdx.x * blockDim.x + threadIdx.x;
    if (e >= n_edges) return;
    int d = g_idx64 ? (int)((const long long*)dst_idx)[e]
                    : ((const int*)dst_idx)[e];
    atomicAdd(&g_cnt[d], 1);
}

// Block-local exclusive scan; writes partial offsets + cursors + block totals.
__global__ void scan1_kernel() {
    __shared__ int s[256];
    int t = threadIdx.x, gid = blockIdx.x * 256 + t;
    int v = g_cnt[gid];
    s[t] = v;
    __syncthreads();
#pragma unroll
    for (int o = 1; o < 256; o <<= 1) {
        int x = (t >= o) ? s[t - o] : 0;
        __syncthreads();
        s[t] += x;
        __syncthreads();
    }
    int excl = s[t] - v;
    g_off[gid] = excl;
    g_cur[gid] = excl;
    if (t == 255) g_bsum[blockIdx.x] = s[255];
}

// Exclusive scan of block sums (in place).
__global__ void scan2_kernel() {
    __shared__ int s[512];
    int t = threadIdx.x;
    int v = (t < SCAN_BLKS) ? g_bsum[t] : 0;
    s[t] = v;
    __syncthreads();
#pragma unroll
    for (int o = 1; o < 512; o <<= 1) {
        int x = (t >= o) ? s[t - o] : 0;
        __syncthreads();
        s[t] += x;
        __syncthreads();
    }
    if (t < SCAN_BLKS) g_bsum[t] = s[t] - v;
}

// Placement: bucket src by dst; absolute index = local cursor + block base.
__global__ void place_kernel(const void* __restrict__ src_idx,
                             const void* __restrict__ dst_idx, int n_edges) {
    int e = blockIdx.x * blockDim.x + threadIdx.x;
    if (e >= n_edges) return;
    int s, d;
    if (g_idx64) {
        s = (int)((const long long*)src_idx)[e];
        d = (int)((const long long*)dst_idx)[e];
    } else {
        s = ((const int*)src_idx)[e];
        d = ((const int*)dst_idx)[e];
    }
    int pos = atomicAdd(&g_cur[d], 1) + g_bsum[d >> 8];
    g_sorted[pos] = s;
}

// ---------------------------------------------------------------------------
// Gather (fp16 neighbor rows, 8 B/lane/edge) + fp32 self + L2-normalize.
// One warp per node, lane holds 4 columns. Writes tf32-rounded h rows.
// ---------------------------------------------------------------------------
__global__ __launch_bounds__(256)
void gather_norm_kernel(const float* __restrict__ feat,
                        const unsigned char* __restrict__ mask) {
    int n = blockIdx.x * 8 + (threadIdx.x >> 5);
    int lane = threadIdx.x & 31;
    if (n >= N_NODES) return;
    int mstride = g_mask_stride;

    float4 acc = ((const float4*)feat)[(size_t)n * 32 + lane];

    if (mask[(size_t)n * mstride]) {
        int beg = g_off[n] + g_bsum[n >> 8];
        int end = g_off[n + 1] + g_bsum[(n + 1) >> 8];
        const __half2* fh = g_fh;
        int e = beg;
        for (; e + 4 <= end; e += 4) {
            int s0 = g_sorted[e + 0], s1 = g_sorted[e + 1];
            int s2 = g_sorted[e + 2], s3 = g_sorted[e + 3];
            // each lane: 2 half2 = 4 cols = 8 bytes per edge
            __half2 a0 = fh[(size_t)s0 * 64 + 2 * lane];
            __half2 b0 = fh[(size_t)s0 * 64 + 2 * lane + 1];
            __half2 a1 = fh[(size_t)s1 * 64 + 2 * lane];
            __half2 b1 = fh[(size_t)s1 * 64 + 2 * lane + 1];
            __half2 a2 = fh[(size_t)s2 * 64 + 2 * lane];
            __half2 b2 = fh[(size_t)s2 * 64 + 2 * lane + 1];
            __half2 a3 = fh[(size_t)s3 * 64 + 2 * lane];
            __half2 b3 = fh[(size_t)s3 * 64 + 2 * lane + 1];
            float2 f;
            f = __half22float2(a0); acc.x += f.x; acc.y += f.y;
            f = __half22float2(b0); acc.z += f.x; acc.w += f.y;
            f = __half22float2(a1); acc.x += f.x; acc.y += f.y;
            f = __half22float2(b1); acc.z += f.x; acc.w += f.y;
            f = __half22float2(a2); acc.x += f.x; acc.y += f.y;
            f = __half22float2(b2); acc.z += f.x; acc.w += f.y;
            f = __half22float2(a3); acc.x += f.x; acc.y += f.y;
            f = __half22float2(b3); acc.z += f.x; acc.w += f.y;
        }
        for (; e < end; e++) {
            int s0 = g_sorted[e];
            __half2 a0 = fh[(size_t)s0 * 64 + 2 * lane];
            __half2 b0 = fh[(size_t)s0 * 64 + 2 * lane + 1];
            float2 f;
            f = __half22float2(a0); acc.x += f.x; acc.y += f.y;
            f = __half22float2(b0); acc.z += f.x; acc.w += f.y;
        }
    }

    float ss = acc.x * acc.x + acc.y * acc.y + acc.z * acc.z + acc.w * acc.w;
#pragma unroll
    for (int o = 16; o > 0; o >>= 1) ss += __shfl_xor_sync(0xFFFFFFFFu, ss, o);
    float inv = 1.f / fmaxf(sqrtf(ss), 1e-12f);

    float4 r;
    r.x = f2tf32f(acc.x * inv);
    r.y = f2tf32f(acc.y * inv);
    r.z = f2tf32f(acc.z * inv);
    r.w = f2tf32f(acc.w * inv);
    ((float4*)g_h)[(size_t)n * 32 + lane] = r;
}

// ---------------------------------------------------------------------------
// GEMM via mma.sync.m16n8k8.tf32 (legacy HMMA path, sm_80+ base PTX).
// Block: 128 threads = 4 warps, tile = 64 nodes x 128 outputs.
// Warp (wm=wid&1, wn=wid>>1): 32 nodes x 64 outputs = 2 m-tiles x 8 n-tiles.
// Fragment LDS with stride WS=132: bank = (4*row + col) mod 32 -> conflict-free.
// ---------------------------------------------------------------------------
__device__ __forceinline__ void mma_tf32(float* d, const uint32_t* a,
                                         uint32_t b0, uint32_t b1) {
    asm volatile(
        "mma.sync.aligned.m16n8k8.row.col.f32.tf32.tf32.f32 "
        "{%0,%1,%2,%3}, {%4,%5,%6,%7}, {%8,%9}, {%0,%1,%2,%3};"
        : "+f"(d[0]), "+f"(d[1]), "+f"(d[2]), "+f"(d[3])
        : "r"(a[0]), "r"(a[1]), "r"(a[2]), "r"(a[3]), "r"(b0), "r"(b1));
}

__global__ __launch_bounds__(128)
void gemm_kernel(const float* __restrict__ W,
                 const float* __restrict__ b,
                 float* __restrict__ out) {
    extern __shared__ float sm[];
    float* Wsm = sm;                  // 128 * WS
    float* Hs  = sm + 128 * WS;       // 64 * WS
    float* bsm = Hs + NB * WS;        // 128

    int t = threadIdx.x;
    int lane = t & 31, wid = t >> 5;
    int grp = lane >> 2, tg = lane & 3;
    int wm = wid & 1, wn = wid >> 1;

    // Stage W (tf32-rounded) once per block.
    for (int idx = t; idx < 128 * 128; idx += 128) {
        int r = idx >> 7, c = idx & 127;
        Wsm[r * WS + c] = f2tf32f(W[idx]);
    }
    if (t < 128) bsm[t] = b[t];
    __syncthreads();

    for (int g = blockIdx.x; g < NUM_TILES; g += gridDim.x) {
        int base = g * NB;

        // Stage normalized h tile (already tf32-rounded).
        for (int idx = t; idx < NB * 32; idx += 128) {
            int nl = idx >> 5, c4 = idx & 31;
            int n = base + nl;
            float4 v = make_float4(0.f, 0.f, 0.f, 0.f);
            if (n < N_NODES) v = ((const float4*)g_h)[(size_t)n * 32 + c4];
            *(float4*)&Hs[nl * WS + c4 * 4] = v;
        }
        __syncthreads();

        float d[2][8][4];
#pragma unroll
        for (int mt = 0; mt < 2; mt++)
#pragma unroll
            for (int nt = 0; nt < 8; nt++)
#pragma unroll
                for (int q = 0; q < 4; q++) d[mt][nt][q] = 0.f;

#pragma unroll
        for (int ks = 0; ks < 16; ks++) {
            int k0 = ks * 8;
            uint32_t a[2][4];
#pragma unroll
            for (int mt = 0; mt < 2; mt++) {
                const float* ar = Hs + (wm * 32 + mt * 16 + grp) * WS + k0 + tg;
                a[mt][0] = __float_as_uint(ar[0]);
                a[mt][1] = __float_as_uint(ar[8 * WS]);
                a[mt][2] = __float_as_uint(ar[4]);
                a[mt][3] = __float_as_uint(ar[8 * WS + 4]);
            }
#pragma unroll
            for (int nt = 0; nt < 8; nt++) {
                const float* br = Wsm + (wn * 64 + nt * 8 + grp) * WS + k0 + tg;
                uint32_t b0 = __float_as_uint(br[0]);
                uint32_t b1 = __float_as_uint(br[4]);
                mma_tf32(d[0][nt], a[0], b0, b1);
                mma_tf32(d[1][nt], a[1], b0, b1);
            }
        }

        // Epilogue: add bias, float2 stores.
#pragma unroll
        for (int mt = 0; mt < 2; mt++) {
            int r0 = base + wm * 32 + mt * 16 + grp;
            int r1 = r0 + 8;
#pragma unroll
            for (int nt = 0; nt < 8; nt++) {
                int col = wn * 64 + nt * 8 + 2 * tg;
                float2 bias = *(float2*)&bsm[col];
                if (r0 < N_NODES) {
                    float2 v = make_float2(d[mt][nt][0] + bias.x,
                                           d[mt][nt][1] + bias.y);
                    *(float2*)&out[(size_t)r0 * D + col] = v;
                }
                if (r1 < N_NODES) {
                    float2 v = make_float2(d[mt][nt][2] + bias.x,
                                           d[mt][nt][3] + bias.y);
                    *(float2*)&out[(size_t)r1 * D + col] = v;
                }
            }
        }
        __syncthreads();
    }
}

// ---------------------------------------------------------------------------
extern "C" void kernel_launch(void* const* d_in, const int* in_sizes, int n_in,
                              void* d_out, int out_size) {
    const float*         feat = (const float*)d_in[0];
    const void*          esrc = d_in[1];
    const void*          edst = d_in[2];
    const unsigned char* mask = (const unsigned char*)d_in[3];
    const float*         W    = (const float*)d_in[4];
    const float*         b    = (const float*)d_in[5];
    float*               out  = (float*)d_out;
    int n_edges = in_sizes[1];

    prologue_kernel<<<1024, 256>>>((const unsigned long long*)esrc, mask, feat);

    int eblk = (n_edges + 255) / 256;
    hist_kernel<<<eblk, 256>>>(edst, n_edges);
    scan1_kernel<<<SCAN_BLKS, 256>>>();
    scan2_kernel<<<1, 512>>>();
    place_kernel<<<eblk, 256>>>(esrc, edst, n_edges);

    gather_norm_kernel<<<(N_NODES + 7) / 8, 256>>>(feat, mask);

    size_t smem = (size_t)(128 * WS + NB * WS + 128) * sizeof(float);
    cudaFuncSetAttribute(gemm_kernel,
                         cudaFuncAttributeMaxDynamicSharedMemorySize,
                         (int)smem);
    gemm_kernel<<<296, 128, smem>>>(W, b, out);
}